// round 1
// baseline (speedup 1.0000x reference)
#include <cuda_runtime.h>

#define BATCH 32
#define CH    512
#define HH    64
#define WW    64
#define KSEL  256           // RATIO 0.5 * 512
#define PLANE (HH * WW)     // 4096

// Scratch (allocation-free rule: __device__ globals)
__device__ float g_scores[BATCH * CH];
__device__ int   g_idx[BATCH * KSEL];

// ---------------------------------------------------------------------------
// Kernel 1: per-(b,c) plane curvature score = sum |valid 3x3 xcorr response|
// One block per plane. Stage plane in smem, sliding-window conv (3 LDS/output),
// per-thread fp32 partial, block reduction in fp64 (rank-stability near the
// top-k boundary).
// ---------------------------------------------------------------------------
__global__ __launch_bounds__(256) void score_kernel(const float* __restrict__ x,
                                                    const float* __restrict__ wgt) {
    __shared__ float  tile[PLANE];
    __shared__ float  w[9];
    __shared__ double sd[256];

    const int tid   = threadIdx.x;
    const int plane = blockIdx.x;

    // Stage 16KB plane with float4 loads
    const float4* src = reinterpret_cast<const float4*>(x) + (size_t)plane * (PLANE / 4);
    float4* dst = reinterpret_cast<float4*>(tile);
    #pragma unroll
    for (int i = tid; i < PLANE / 4; i += 256) dst[i] = src[i];
    if (tid < 9) w[tid] = wgt[tid];
    __syncthreads();

    // 62 output rows x 4 column segments = 248 work items
    double acc = 0.0;
    if (tid < 248) {
        const int r  = tid >> 2;
        const int s  = tid & 3;
        const int c0 = s * 16;
        const int c1 = (s == 3) ? 62 : (c0 + 16);

        const float* t0 = tile + r * WW;
        const float* t1 = t0 + WW;
        const float* t2 = t1 + WW;

        const float w0 = w[0], w1 = w[1], w2 = w[2];
        const float w3 = w[3], w4 = w[4], w5 = w[5];
        const float w6 = w[6], w7 = w[7], w8 = w[8];

        float a0 = t0[c0], b0 = t0[c0 + 1];
        float a1 = t1[c0], b1 = t1[c0 + 1];
        float a2 = t2[c0], b2 = t2[c0 + 1];

        float facc = 0.0f;
        #pragma unroll 4
        for (int c = c0; c < c1; ++c) {
            const float n0 = t0[c + 2];
            const float n1 = t1[c + 2];
            const float n2 = t2[c + 2];
            float conv = w0 * a0;
            conv = fmaf(w1, b0, conv);
            conv = fmaf(w2, n0, conv);
            conv = fmaf(w3, a1, conv);
            conv = fmaf(w4, b1, conv);
            conv = fmaf(w5, n1, conv);
            conv = fmaf(w6, a2, conv);
            conv = fmaf(w7, b2, conv);
            conv = fmaf(w8, n2, conv);
            facc += fabsf(conv);
            a0 = b0; b0 = n0;
            a1 = b1; b1 = n1;
            a2 = b2; b2 = n2;
        }
        acc = (double)facc;
    }

    sd[tid] = acc;
    __syncthreads();
    #pragma unroll
    for (int off = 128; off > 0; off >>= 1) {
        if (tid < off) sd[tid] += sd[tid + off];
        __syncthreads();
    }
    if (tid == 0) g_scores[plane] = (float)sd[0];
}

// ---------------------------------------------------------------------------
// Kernel 2: per-batch top-k (k=256) via exact rank counting.
// rank = #(score strictly greater) + #(equal score with lower channel index),
// which reproduces lax.top_k ordering (descending value, ties -> lower index).
// ---------------------------------------------------------------------------
__global__ __launch_bounds__(512) void topk_kernel() {
    __shared__ float s[CH];
    const int b   = blockIdx.x;
    const int tid = threadIdx.x;

    s[tid] = g_scores[b * CH + tid];
    __syncthreads();

    const float my = s[tid];
    int rank = 0;
    #pragma unroll 8
    for (int j = 0; j < CH; ++j) {
        const float v = s[j];
        rank += (v > my) || (v == my && j < tid);
    }
    if (rank < KSEL) g_idx[b * KSEL + rank] = tid;
}

// ---------------------------------------------------------------------------
// Kernel 3: gather selected channel planes (contiguous 16KB float4 copies).
// ---------------------------------------------------------------------------
__global__ __launch_bounds__(256) void gather_kernel(const float* __restrict__ x,
                                                     float* __restrict__ out) {
    const int b = blockIdx.y;
    const int r = blockIdx.x;
    const int c = g_idx[b * KSEL + r];   // broadcast

    const float4* src = reinterpret_cast<const float4*>(x)
                        + ((size_t)(b * CH + c)) * (PLANE / 4);
    float4* dst = reinterpret_cast<float4*>(out)
                  + ((size_t)(b * KSEL + r)) * (PLANE / 4);
    #pragma unroll
    for (int i = threadIdx.x; i < PLANE / 4; i += 256) dst[i] = src[i];
}

extern "C" void kernel_launch(void* const* d_in, const int* in_sizes, int n_in,
                              void* d_out, int out_size) {
    const float* x = (const float*)d_in[0];
    const float* w = (const float*)d_in[1];
    // Defensive: metadata order should be (x, weight); swap if sizes say otherwise.
    if (n_in >= 2 && in_sizes[0] == 9) {
        const float* t = x; x = w; w = t;
    }
    float* out = (float*)d_out;

    score_kernel<<<BATCH * CH, 256>>>(x, w);
    topk_kernel<<<BATCH, 512>>>();
    gather_kernel<<<dim3(KSEL, BATCH), 256>>>(x, out);
}

// round 2
// speedup vs baseline: 3.5661x; 3.5661x over previous
#include <cuda_runtime.h>

#define BATCH 32
#define CH    512
#define HH    64
#define WW    64
#define KSEL  256           // RATIO 0.5 * 512
#define PLANE (HH * WW)     // 4096

// Scratch (allocation-free rule: __device__ globals)
__device__ float g_scores[BATCH * CH];
__device__ int   g_idx[BATCH * KSEL];

// ---------------------------------------------------------------------------
// Kernel 1: per-(b,c) plane curvature score = sum |valid 3x3 xcorr response|
// One block (256 thr = 8 warps) per plane.
//  - stage 16KB plane to smem via float4
//  - warp w handles output rows [w*8, w*8+nrows); lanes are contiguous column
//    pairs (lane -> cols 2l, 2l+1): LDS.64 per input row is conflict-free,
//    +1/+2 column neighbors come from __shfl_down (no extra LDS),
//    rows slide through registers (each input row read from smem once/warp).
//  - per-thread fp32 partial, warp fp64 shuffle-reduce, 8 partials -> fp64.
// ---------------------------------------------------------------------------
__global__ __launch_bounds__(256) void score_kernel(const float* __restrict__ x,
                                                    const float* __restrict__ wgt) {
    __shared__ float  tile[PLANE];
    __shared__ float  sw[9];
    __shared__ double swarp[8];

    const int tid   = threadIdx.x;
    const int plane = blockIdx.x;

    // Stage 16KB plane with float4 loads (coalesced, conflict-free STS.128)
    const float4* src = reinterpret_cast<const float4*>(x) + (size_t)plane * (PLANE / 4);
    float4* dst = reinterpret_cast<float4*>(tile);
    #pragma unroll
    for (int i = 0; i < PLANE / 4 / 256; ++i) dst[tid + i * 256] = src[tid + i * 256];
    if (tid < 9) sw[tid] = wgt[tid];
    __syncthreads();

    const int lane = tid & 31;
    const int warp = tid >> 5;
    const int r0    = warp * 8;                 // first output row of this warp
    const int nrows = (warp == 7) ? 6 : 8;      // 7*8 + 6 = 62 output rows

    const float w0 = sw[0], w1 = sw[1], w2 = sw[2];
    const float w3 = sw[3], w4 = sw[4], w5 = sw[5];
    const float w6 = sw[6], w7 = sw[7], w8 = sw[8];

    // lane owns input columns 2l, 2l+1 ; neighbor columns 2l+2, 2l+3 via shfl
    const float2* t2 = reinterpret_cast<const float2*>(tile);
    const unsigned FULL = 0xffffffffu;

    float2 a = t2[(r0    ) * 32 + lane];
    float2 b = t2[(r0 + 1) * 32 + lane];
    float anx = __shfl_down_sync(FULL, a.x, 1);
    float any = __shfl_down_sync(FULL, a.y, 1);
    float bnx = __shfl_down_sync(FULL, b.x, 1);
    float bny = __shfl_down_sync(FULL, b.y, 1);

    float facc = 0.0f;
    for (int i = 0; i < nrows; ++i) {
        const float2 c = t2[(r0 + i + 2) * 32 + lane];
        const float cnx = __shfl_down_sync(FULL, c.x, 1);
        const float cny = __shfl_down_sync(FULL, c.y, 1);

        if (lane < 31) {   // lane 31 only supplies shuffle data (cols 62/63 invalid)
            // output column 2l: inputs cols 2l..2l+2 of rows r..r+2
            float conv0 = w0 * a.x;
            conv0 = fmaf(w1, a.y, conv0);
            conv0 = fmaf(w2, anx, conv0);
            conv0 = fmaf(w3, b.x, conv0);
            conv0 = fmaf(w4, b.y, conv0);
            conv0 = fmaf(w5, bnx, conv0);
            conv0 = fmaf(w6, c.x, conv0);
            conv0 = fmaf(w7, c.y, conv0);
            conv0 = fmaf(w8, cnx, conv0);
            // output column 2l+1: inputs cols 2l+1..2l+3
            float conv1 = w0 * a.y;
            conv1 = fmaf(w1, anx, conv1);
            conv1 = fmaf(w2, any, conv1);
            conv1 = fmaf(w3, b.y, conv1);
            conv1 = fmaf(w4, bnx, conv1);
            conv1 = fmaf(w5, bny, conv1);
            conv1 = fmaf(w6, c.y, conv1);
            conv1 = fmaf(w7, cnx, conv1);
            conv1 = fmaf(w8, cny, conv1);
            facc += fabsf(conv0);
            facc += fabsf(conv1);
        }
        a = b;  anx = bnx;  any = bny;
        b = c;  bnx = cnx;  bny = cny;
    }

    // fp64 reduction: warp shuffle tree, then 8 partials
    double acc = (double)facc;
    #pragma unroll
    for (int off = 16; off > 0; off >>= 1)
        acc += __shfl_xor_sync(FULL, acc, off);
    if (lane == 0) swarp[warp] = acc;
    __syncthreads();
    if (tid == 0) {
        double s = 0.0;
        #pragma unroll
        for (int i = 0; i < 8; ++i) s += swarp[i];
        g_scores[plane] = (float)s;
    }
}

// ---------------------------------------------------------------------------
// Kernel 2: per-batch top-k (k=256) via exact rank counting.
// rank = #(score strictly greater) + #(equal score with lower channel index),
// which reproduces lax.top_k ordering (descending value, ties -> lower index).
// ---------------------------------------------------------------------------
__global__ __launch_bounds__(512) void topk_kernel() {
    __shared__ float s[CH];
    const int b   = blockIdx.x;
    const int tid = threadIdx.x;

    s[tid] = g_scores[b * CH + tid];
    __syncthreads();

    const float my = s[tid];
    int rank = 0;
    #pragma unroll 8
    for (int j = 0; j < CH; ++j) {
        const float v = s[j];
        rank += (v > my) || (v == my && j < tid);
    }
    if (rank < KSEL) g_idx[b * KSEL + rank] = tid;
}

// ---------------------------------------------------------------------------
// Kernel 3: gather selected channel planes (contiguous 16KB float4 copies).
// ---------------------------------------------------------------------------
__global__ __launch_bounds__(256) void gather_kernel(const float* __restrict__ x,
                                                     float* __restrict__ out) {
    const int b = blockIdx.y;
    const int r = blockIdx.x;
    const int c = g_idx[b * KSEL + r];   // broadcast

    const float4* src = reinterpret_cast<const float4*>(x)
                        + ((size_t)(b * CH + c)) * (PLANE / 4);
    float4* dst = reinterpret_cast<float4*>(out)
                  + ((size_t)(b * KSEL + r)) * (PLANE / 4);
    #pragma unroll
    for (int i = threadIdx.x; i < PLANE / 4; i += 256) dst[i] = src[i];
}

extern "C" void kernel_launch(void* const* d_in, const int* in_sizes, int n_in,
                              void* d_out, int out_size) {
    const float* x = (const float*)d_in[0];
    const float* w = (const float*)d_in[1];
    // Defensive: metadata order should be (x, weight); swap if sizes say otherwise.
    if (n_in >= 2 && in_sizes[0] == 9) {
        const float* t = x; x = w; w = t;
    }
    float* out = (float*)d_out;

    score_kernel<<<BATCH * CH, 256>>>(x, w);
    topk_kernel<<<BATCH, 512>>>();
    gather_kernel<<<dim3(KSEL, BATCH), 256>>>(x, out);
}